// round 5
// baseline (speedup 1.0000x reference)
#include <cuda_runtime.h>
#include <cstdint>

#define BSZ 256
#define TLEN 512
#define KTAG 48
#define KK (KTAG*KTAG)          // 2304 floats per (b,t) tile
#define PAD 52                  // padded row stride (floats) -> conflict-free LDS
#define START_TAG 46
#define END_TAG 47
#define ROWS_PER 6
#define NTHREADS 384
#define NBUF 8                  // prefetch ring (power of two)
#define PF 6                    // groups primed; consume lead = PF-2 = 4 tiles
#define CPR 12                  // 16B chunks per row
#define CHUNKS (KTAG*CPR)       // 576
#define TILE_F (KTAG*PAD)       // floats per padded tile
#define L2E 1.44269504088896f
#define LN2 0.6931471805599453f

__device__ float g_partial[BSZ];
__device__ unsigned int g_count;   // zero-init; reset to 0 by the reducing CTA

__device__ __forceinline__ void cp16(uint32_t dst_smem, const void* src) {
    asm volatile("cp.async.cg.shared.global [%0], [%1], 16;" :: "r"(dst_smem), "l"(src));
}
__device__ __forceinline__ void cp_commit() {
    asm volatile("cp.async.commit_group;" ::: "memory");
}
template<int N>
__device__ __forceinline__ void cp_wait() {
    asm volatile("cp.async.wait_group %0;" :: "n"(N) : "memory");
}
__device__ __forceinline__ float fast_ex2(float x) {
    float r; asm("ex2.approx.ftz.f32 %0, %1;" : "=f"(r) : "f"(x)); return r;
}
__device__ __forceinline__ float fast_lg2(float x) {
    float r; asm("lg2.approx.ftz.f32 %0, %1;" : "=f"(r) : "f"(x)); return r;
}
__device__ __forceinline__ float fast_rcp(float x) {
    float r; asm("rcp.approx.ftz.f32 %0, %1;" : "=f"(r) : "f"(x)); return r;
}

__global__ __launch_bounds__(NTHREADS, 2)
void crf_fwd_kernel(const float* __restrict__ scores,
                    const int* __restrict__ targets,
                    const int* __restrict__ lengths,
                    float* __restrict__ out)
{
    extern __shared__ float sdyn[];
    float* buf   = sdyn;                         // NBUF * TILE_F
    float* eag2  = buf + NBUF * TILE_F;          // 2 * KTAG (exp-domain agg, ping-pong)
    int*   tgt_s = (int*)(eag2 + 2 * KTAG);      // TLEN

    const int bid = blockIdx.x;
    // SM k classically hosts bids k and k+148 -> pair batch s with 255-s (lengths sorted desc).
    const int b = (bid < 148) ? bid : (403 - bid);

    const int tid = threadIdx.x;
    const int j   = tid >> 3;          // column 0..47
    const int y   = tid & 7;           // row-group 0..7 (8 partials within one warp)
    const int i0  = y * ROWS_PER;
    const int len = lengths[b];

    const float* base = scores + (size_t)b * TLEN * KK;

    for (int t = tid; t < len; t += NTHREADS) {
        int tg = targets[b * TLEN + t];
        tgt_s[t] = (tg / KTAG) * PAD + (tg % KTAG);
    }

    // per-thread cp.async chunk offsets
    const uint32_t sbase = (uint32_t)__cvta_generic_to_shared(buf);
    const int r0 = tid / CPR, p0 = tid % CPR;
    const uint32_t dst0 = (uint32_t)(r0 * (PAD * 4) + p0 * 16);
    const size_t  so0  = (size_t)tid * 16;
    const bool two = (tid < CHUNKS - NTHREADS);
    const int c1 = tid + NTHREADS;
    const int r1 = c1 / CPR, p1 = c1 % CPR;
    const uint32_t dst1 = (uint32_t)(r1 * (PAD * 4) + p1 * 16);
    const size_t  so1  = (size_t)c1 * 16;

    auto issue = [&](int t) {
        const char* s = (const char*)(base + (size_t)t * KK);
        uint32_t d = sbase + (uint32_t)(t & (NBUF - 1)) * (TILE_F * 4);
        cp16(d + dst0, s + so0);
        if (two) cp16(d + dst1, s + so1);
    };

    // prime tiles 0..PF-1 (always PF commits so group counts stay fixed)
    #pragma unroll
    for (int k = 0; k < PF; ++k) {
        if (k < len) issue(k);
        cp_commit();
    }
    cp_wait<PF - 2>();          // my chunks of tiles 0,1 done
    __syncthreads();            // everyone's chunks of tiles 0,1 + tgt_s visible

    // t = 0: eag_1[j] = 2^(score[START,j]*log2e), N_1 = 0
    if (y == 0)
        eag2[KTAG + j] = fast_ex2(buf[START_TAG * PAD + j] * L2E);

    float esc[ROWS_PER];
    if (len > 1) {
        const float* t1 = buf + TILE_F;
        #pragma unroll
        for (int k = 0; k < ROWS_PER; ++k)
            esc[k] = fast_ex2(t1[(i0 + k) * PAD + j] * L2E);
    }
    float true_sum = (tid == 0) ? buf[tgt_s[0]] : 0.0f;
    float N = 0.0f;

    for (int t = 1; t < len; ++t) {
        __syncthreads();                         // publishes eag_t (slot t&1)

        const float* eag = eag2 + (t & 1) * KTAG;
        const float e0v = eag[0];
        const float rcp = fast_rcp(e0v);         // latency hidden under dot+shuffles
        const float lg  = fast_lg2(e0v);         // off critical path

        // dot: s_part = sum_k esc[k] * eag[i0+k]   (all positive)
        float a0 = fmaf(esc[1], eag[i0 + 1], esc[0] * eag[i0 + 0]);
        float a1 = fmaf(esc[3], eag[i0 + 3], esc[2] * eag[i0 + 2]);
        float a2 = fmaf(esc[5], eag[i0 + 5], esc[4] * eag[i0 + 4]);
        float s = (a0 + a1) + a2;

        // prefetch + next-step esc: issued here so EX2/LDS hide under the SHFL chain
        if (t + PF - 1 < len) issue(t + PF - 1);
        cp_commit();
        cp_wait<PF - 2>();                       // tile t+1 resident (lead = 4 tiles)

        const float* ntile = buf + ((t + 1) & (NBUF - 1)) * TILE_F;
        float nesc[ROWS_PER];
        #pragma unroll
        for (int k = 0; k < ROWS_PER; ++k)
            nesc[k] = fast_ex2(ntile[(i0 + k) * PAD + j] * L2E);

        if (tid == 0) true_sum += (buf + (t & (NBUF - 1)) * TILE_F)[tgt_s[t]];

        // merge 8 partials (lanes differ only in y-bits within the warp)
        s += __shfl_xor_sync(0xffffffffu, s, 1);
        s += __shfl_xor_sync(0xffffffffu, s, 2);
        s += __shfl_xor_sync(0xffffffffu, s, 4);

        if (y == 0)
            eag2[((t + 1) & 1) * KTAG + j] = s * rcp;   // 2^(G_{t+1}[j] - G_t[0])
        N += lg;                                         // N_{t+1} = N_t + lg2(eag_t[0])

        #pragma unroll
        for (int k = 0; k < ROWS_PER; ++k) esc[k] = nesc[k];
    }

    __syncthreads();
    if (tid == 0)
        g_partial[b] = (fast_lg2(eag2[(len & 1) * KTAG + END_TAG]) + N) * LN2 - true_sum;

    // last CTA reduces (deterministic: fixed strided order + fixed warp tree)
    if (tid < 32) {
        unsigned done = 0;
        if (tid == 0) {
            __threadfence();
            done = atomicAdd(&g_count, 1u);
        }
        done = __shfl_sync(0xffffffffu, done, 0);
        if (done == BSZ - 1) {
            __threadfence();
            const volatile float* gp = g_partial;
            float s = 0.0f;
            #pragma unroll
            for (int k = 0; k < BSZ / 32; ++k) s += gp[tid + 32 * k];
            s += __shfl_xor_sync(0xffffffffu, s, 16);
            s += __shfl_xor_sync(0xffffffffu, s, 8);
            s += __shfl_xor_sync(0xffffffffu, s, 4);
            s += __shfl_xor_sync(0xffffffffu, s, 2);
            s += __shfl_xor_sync(0xffffffffu, s, 1);
            if (tid == 0) {
                out[0] = s / (float)BSZ;
                g_count = 0;                      // reset for next graph replay
            }
        }
    }
}

extern "C" void kernel_launch(void* const* d_in, const int* in_sizes, int n_in,
                              void* d_out, int out_size)
{
    const float* scores  = (const float*)d_in[0];
    const int*   targets = (const int*)d_in[1];
    const int*   lengths = (const int*)d_in[2];
    float* out = (float*)d_out;

    const int smem_bytes = (NBUF * TILE_F + 2 * KTAG) * 4 + TLEN * 4;
    cudaFuncSetAttribute(crf_fwd_kernel,
                         cudaFuncAttributeMaxDynamicSharedMemorySize, smem_bytes);

    crf_fwd_kernel<<<BSZ, NTHREADS, smem_bytes>>>(scores, targets, lengths, out);
}